// round 12
// baseline (speedup 1.0000x reference)
#include <cuda_runtime.h>
#include <cuda_fp16.h>
#include <cstdint>

// ClusteredLinear via fp16 mma.sync GEMM, one channel per CTA.
// out[b,c,p] = sum_s x[b,c,s]*W[cl[c],p,s] + bias[cl[c],p]
// R11: R10 config (128 thr / 4 warps, 2Mx2N m32n56, KC=32) with NSTAGES=3
// -> 42.2KB smem -> 5 CTAs/SM (was 4): one more independent pipeline per SM
// to hide the cp.wait/LDSM latency that keeps gemm ~2x above its crossbar
// floor. Stage=14KB so wait(1) still leaves ~2 chunk-times of load slack
// (R7's 3-stage failure had 53KB stages — different regime).
// Single-pass fp16 (x,W rounded, fp32 accum): rel_err ~3.0e-4 measured.

#define B_DIM 64
#define C_DIM 862
#define S_DIM 720
#define P_DIM 336
#define NCLUST 8

#define TILE_N 112
#define KC 32
#define NCHUNKS 23          // 22 full + 16-elem zero-padded tail
#define NSTAGES 3

#define ROWB 80                       // padded smem row stride (bytes)
#define OFF_A 0
#define OFF_B (64*ROWB)               // 5120
#define STAGE_B (OFF_B + TILE_N*ROWB)    // 14080
#define SMEM_TOTAL (NSTAGES*STAGE_B)     // 42240

// ---- scratch ----
__device__ __half g_xh[(size_t)B_DIM*C_DIM*S_DIM];
__device__ __half g_wh[(size_t)NCLUST*P_DIM*S_DIM];

// ---- PTX helpers (family-portable) ----
__device__ __forceinline__ uint32_t smem_u32(const void* p) {
    uint32_t a;
    asm("{ .reg .u64 t; cvta.to.shared.u64 t, %1; cvt.u32.u64 %0, t; }" : "=r"(a) : "l"(p));
    return a;
}
#define CP16(dst,src) asm volatile("cp.async.cg.shared.global [%0], [%1], 16;" :: "r"(dst), "l"(src) : "memory")
#define CP_COMMIT()   asm volatile("cp.async.commit_group;" ::: "memory")
#define CP_WAIT(n)    asm volatile("cp.async.wait_group %0;" :: "n"(n) : "memory")
#define ZERO16(a)     asm volatile("st.shared.v4.b32 [%0], {%1,%1,%1,%1};" :: "r"(a), "r"(0) : "memory")

#define LDSM4(r, a) asm volatile("ldmatrix.sync.aligned.m8n8.x4.shared.b16 {%0,%1,%2,%3}, [%4];" \
    : "=r"((r)[0]),"=r"((r)[1]),"=r"((r)[2]),"=r"((r)[3]) : "r"(a))
#define LDSM2(r, a) asm volatile("ldmatrix.sync.aligned.m8n8.x2.shared.b16 {%0,%1}, [%2];" \
    : "=r"((r)[0]),"=r"((r)[1]) : "r"(a))
#define MMA(c, a, b) asm volatile( \
    "mma.sync.aligned.m16n8k16.row.col.f32.f16.f16.f32 " \
    "{%0,%1,%2,%3},{%4,%5,%6,%7},{%8,%9},{%0,%1,%2,%3};" \
    : "+f"((c)[0]),"+f"((c)[1]),"+f"((c)[2]),"+f"((c)[3]) \
    : "r"((a)[0]),"r"((a)[1]),"r"((a)[2]),"r"((a)[3]),"r"((b)[0]),"r"((b)[1]))

// ---- prep kernels ----
__global__ void convert_x(const float* __restrict__ src) {
    size_t i = (size_t)blockIdx.x * blockDim.x + threadIdx.x;
    const size_t n4 = (size_t)B_DIM * C_DIM * S_DIM / 4;
    if (i >= n4) return;
    float4 v = ((const float4*)src)[i];
    float vv[4] = {v.x, v.y, v.z, v.w};
    __half h[4];
    #pragma unroll
    for (int j = 0; j < 4; ++j) h[j] = __float2half_rn(vv[j]);
    ((uint2*)g_xh)[i] = *(uint2*)h;
}
__global__ void convert_w(const float* __restrict__ src) {
    size_t i = (size_t)blockIdx.x * blockDim.x + threadIdx.x;
    const size_t n4 = (size_t)NCLUST * P_DIM * S_DIM / 4;
    if (i >= n4) return;
    float4 v = ((const float4*)src)[i];
    float vv[4] = {v.x, v.y, v.z, v.w};
    __half h[4];
    #pragma unroll
    for (int j = 0; j < 4; ++j) h[j] = __float2half_rn(vv[j]);
    ((uint2*)g_wh)[i] = *(uint2*)h;
}

// ---- GEMM ----
__device__ __forceinline__ void load_stage(uint32_t st, int k0, bool tail,
                                           int ch, int kcl,
                                           int n_base, int tid) {
    // A: 64 rows x 64B of K. 256 slots over 128 threads.
    #pragma unroll
    for (int v = tid; v < 256; v += 128) {
        int r = v >> 2, q = v & 3;
        size_t so = ((size_t)r * C_DIM + ch) * S_DIM + k0 + q * 8;
        uint32_t d = st + OFF_A + r * ROWB + q * 16;
        if (!tail || q < 2) CP16(d, g_xh + so);
        else                ZERO16(d);
    }
    // B: 112 rows x 64B of K. 448 slots over 128 threads.
    #pragma unroll
    for (int v = tid; v < 448; v += 128) {
        int r = v >> 2, q = v & 3;
        size_t so = ((size_t)kcl * P_DIM + n_base + r) * S_DIM + k0 + q * 8;
        uint32_t d = st + OFF_B + r * ROWB + q * 16;
        if (!tail || q < 2) CP16(d, g_wh + so);
        else                ZERO16(d);
    }
}

__global__ __launch_bounds__(128, 5)
void gemm_kernel(const int* __restrict__ clusters,
                 const float* __restrict__ bias,
                 float* __restrict__ out) {
    extern __shared__ char smem[];
    const uint32_t sbase = smem_u32(smem);
    const int tid  = threadIdx.x;
    const int lane = tid & 31;
    const int wid  = tid >> 5;
    const int warpM = wid & 1;      // 2 M-warps (m32 each)
    const int warpN = wid >> 1;     // 2 N-warps (n56 each)
    const int mrow0 = warpM * 32;
    const int nrow0 = warpN * 56;

    const int ch     = blockIdx.y;           // channel
    const int n_base = blockIdx.x * TILE_N;

    int kcl = clusters[ch];
    kcl = min(max(kcl, 0), NCLUST - 1);

    float acc[2][7][4] = {};

    // ldmatrix base addresses (stage 0; add stage offset per chunk).
    const uint32_t a_addr0 = sbase + OFF_A +
        (uint32_t)(mrow0 + (lane & 15)) * ROWB + ((lane >> 4) << 4);
    const uint32_t b_addr_pair0 = sbase + OFF_B +
        (uint32_t)(nrow0 + ((lane >> 4) << 3) + (lane & 7)) * ROWB +
        (((lane >> 3) & 1) << 4);
    const uint32_t b_addr_last0 = sbase + OFF_B +
        (uint32_t)(nrow0 + 48 + (lane & 7)) * ROWB + (((lane >> 3) & 1) << 4);

    // prologue: stages 0..NSTAGES-2
    #pragma unroll
    for (int s = 0; s < NSTAGES - 1; ++s) {
        load_stage(sbase + s * STAGE_B, s * KC, false, ch, kcl, n_base, tid);
        CP_COMMIT();
    }

    int stage = 0;
    for (int chunk = 0; chunk < NCHUNKS; ++chunk) {
        CP_WAIT(NSTAGES - 2);
        __syncthreads();

        const int nx = chunk + NSTAGES - 1;
        if (nx < NCHUNKS) {
            int nstage = stage + NSTAGES - 1;
            if (nstage >= NSTAGES) nstage -= NSTAGES;
            load_stage(sbase + nstage * STAGE_B, nx * KC,
                       nx == NCHUNKS - 1, ch, kcl, n_base, tid);
        }
        CP_COMMIT();

        const uint32_t so = (uint32_t)stage * STAGE_B;
        #pragma unroll
        for (int ks = 0; ks < 2; ++ks) {
            const int kb = ks * 32;
            uint32_t ah[2][4];
            LDSM4(ah[0], a_addr0 + so + kb);
            LDSM4(ah[1], a_addr0 + so + kb + 16 * ROWB);

            uint32_t bh[7][2];
            #pragma unroll
            for (int p = 0; p < 3; ++p) {
                uint32_t a = b_addr_pair0 + so + kb + (uint32_t)p * 16 * ROWB;
                uint32_t r4[4];
                LDSM4(r4, a);
                bh[2*p][0] = r4[0]; bh[2*p][1] = r4[1];
                bh[2*p+1][0] = r4[2]; bh[2*p+1][1] = r4[3];
            }
            LDSM2(bh[6], b_addr_last0 + so + kb);

            #pragma unroll
            for (int mf = 0; mf < 2; ++mf)
                #pragma unroll
                for (int nf = 0; nf < 7; ++nf)
                    MMA(acc[mf][nf], ah[mf], bh[nf]);
        }
        if (++stage == NSTAGES) stage = 0;
    }

    // epilogue: bias + store
    const float* biasrow = bias + (size_t)kcl * P_DIM + n_base + nrow0;
    #pragma unroll
    for (int mf = 0; mf < 2; ++mf) {
        const int b0 = mrow0 + mf * 16 + (lane >> 2);   // batch rows b0, b0+8
        float* o0 = out + ((size_t)b0 * C_DIM + ch) * P_DIM + n_base + nrow0;
        float* o1 = o0 + (size_t)8 * C_DIM * P_DIM;
        #pragma unroll
        for (int nf = 0; nf < 7; ++nf) {
            const int col = nf * 8 + (lane & 3) * 2;
            float2 bb = *(const float2*)(biasrow + col);
            float2 v0, v1;
            v0.x = acc[mf][nf][0] + bb.x;
            v0.y = acc[mf][nf][1] + bb.y;
            v1.x = acc[mf][nf][2] + bb.x;
            v1.y = acc[mf][nf][3] + bb.y;
            *(float2*)(o0 + col) = v0;
            *(float2*)(o1 + col) = v1;
        }
    }
}

extern "C" void kernel_launch(void* const* d_in, const int* in_sizes, int n_in,
                              void* d_out, int out_size) {
    const float* x        = (const float*)d_in[0];
    const int*   clusters = (const int*)d_in[1];
    const float* W        = (const float*)d_in[2];
    const float* bias     = (const float*)d_in[3];
    float*       out      = (float*)d_out;

    cudaFuncSetAttribute(gemm_kernel, cudaFuncAttributeMaxDynamicSharedMemorySize, SMEM_TOTAL);

    convert_x<<<(int)(((size_t)B_DIM*C_DIM*S_DIM/4 + 255)/256), 256>>>(x);
    convert_w<<<(int)(((size_t)NCLUST*P_DIM*S_DIM/4 + 255)/256), 256>>>(W);
    gemm_kernel<<<dim3(3, C_DIM), 128, SMEM_TOTAL>>>(clusters, bias, out);
}

// round 14
// speedup vs baseline: 1.0115x; 1.0115x over previous
#include <cuda_runtime.h>
#include <cuda_fp16.h>
#include <cstdint>

// ClusteredLinear via fp16 mma.sync GEMM, one channel per CTA.
// out[b,c,p] = sum_s x[b,c,s]*W[cl[c],p,s] + bias[cl[c],p]
// R13 = R12 with the __half2_as_uint compile error fixed (bit-cast via
// reinterpret). Exact R10 config (128 thr / 4 warps, 2Mx2N m32n56, KC=32,
// 4 stages, 4 CTAs/SM) plus intra-chunk fragment prefetch: all 24 LDSM for
// both ks halves issue before the 56 MMAs, so ks=1 LDSM latency hides under
// ks=0 MMA execution.
// Single-pass fp16 (x,W rounded, fp32 accum): rel_err ~3.0e-4 measured.

#define B_DIM 64
#define C_DIM 862
#define S_DIM 720
#define P_DIM 336
#define NCLUST 8

#define TILE_N 112
#define KC 32
#define NCHUNKS 23          // 22 full + 16-elem zero-padded tail
#define NSTAGES 4

#define ROWB 80                       // padded smem row stride (bytes)
#define OFF_A 0
#define OFF_B (64*ROWB)               // 5120
#define STAGE_B (OFF_B + TILE_N*ROWB)    // 14080
#define SMEM_TOTAL (NSTAGES*STAGE_B)     // 56320

// ---- scratch ----
__device__ __half g_xh[(size_t)B_DIM*C_DIM*S_DIM];
__device__ __half g_wh[(size_t)NCLUST*P_DIM*S_DIM];

// ---- PTX helpers (family-portable) ----
__device__ __forceinline__ uint32_t smem_u32(const void* p) {
    uint32_t a;
    asm("{ .reg .u64 t; cvta.to.shared.u64 t, %1; cvt.u32.u64 %0, t; }" : "=r"(a) : "l"(p));
    return a;
}
__device__ __forceinline__ uint32_t h2_bits(__half2 h) {
    return *reinterpret_cast<uint32_t*>(&h);
}
#define CP16(dst,src) asm volatile("cp.async.cg.shared.global [%0], [%1], 16;" :: "r"(dst), "l"(src) : "memory")
#define CP_COMMIT()   asm volatile("cp.async.commit_group;" ::: "memory")
#define CP_WAIT(n)    asm volatile("cp.async.wait_group %0;" :: "n"(n) : "memory")
#define ZERO16(a)     asm volatile("st.shared.v4.b32 [%0], {%1,%1,%1,%1};" :: "r"(a), "r"(0) : "memory")

#define LDSM4(r, a) asm volatile("ldmatrix.sync.aligned.m8n8.x4.shared.b16 {%0,%1,%2,%3}, [%4];" \
    : "=r"((r)[0]),"=r"((r)[1]),"=r"((r)[2]),"=r"((r)[3]) : "r"(a))
#define LDSM2(r, a) asm volatile("ldmatrix.sync.aligned.m8n8.x2.shared.b16 {%0,%1}, [%2];" \
    : "=r"((r)[0]),"=r"((r)[1]) : "r"(a))
#define MMA(c, a, b) asm volatile( \
    "mma.sync.aligned.m16n8k16.row.col.f32.f16.f16.f32 " \
    "{%0,%1,%2,%3},{%4,%5,%6,%7},{%8,%9},{%0,%1,%2,%3};" \
    : "+f"((c)[0]),"+f"((c)[1]),"+f"((c)[2]),"+f"((c)[3]) \
    : "r"((a)[0]),"r"((a)[1]),"r"((a)[2]),"r"((a)[3]),"r"((b)[0]),"r"((b)[1]))

// ---- prep kernels ----
__global__ void convert_x(const float* __restrict__ src) {
    size_t i = (size_t)blockIdx.x * blockDim.x + threadIdx.x;
    const size_t n8 = (size_t)B_DIM * C_DIM * S_DIM / 8;
    if (i >= n8) return;
    float4 v0 = ((const float4*)src)[2 * i];
    float4 v1 = ((const float4*)src)[2 * i + 1];
    uint4 o;
    o.x = h2_bits(__floats2half2_rn(v0.x, v0.y));
    o.y = h2_bits(__floats2half2_rn(v0.z, v0.w));
    o.z = h2_bits(__floats2half2_rn(v1.x, v1.y));
    o.w = h2_bits(__floats2half2_rn(v1.z, v1.w));
    ((uint4*)g_xh)[i] = o;
}
__global__ void convert_w(const float* __restrict__ src) {
    size_t i = (size_t)blockIdx.x * blockDim.x + threadIdx.x;
    const size_t n4 = (size_t)NCLUST * P_DIM * S_DIM / 4;
    if (i >= n4) return;
    float4 v = ((const float4*)src)[i];
    uint2 o;
    o.x = h2_bits(__floats2half2_rn(v.x, v.y));
    o.y = h2_bits(__floats2half2_rn(v.z, v.w));
    ((uint2*)g_wh)[i] = o;
}

// ---- GEMM ----
__device__ __forceinline__ void load_stage(uint32_t st, int k0, bool tail,
                                           int ch, int kcl,
                                           int n_base, int tid) {
    // A: 64 rows x 64B of K. 256 slots over 128 threads.
    #pragma unroll
    for (int v = tid; v < 256; v += 128) {
        int r = v >> 2, q = v & 3;
        size_t so = ((size_t)r * C_DIM + ch) * S_DIM + k0 + q * 8;
        uint32_t d = st + OFF_A + r * ROWB + q * 16;
        if (!tail || q < 2) CP16(d, g_xh + so);
        else                ZERO16(d);
    }
    // B: 112 rows x 64B of K. 448 slots over 128 threads.
    #pragma unroll
    for (int v = tid; v < 448; v += 128) {
        int r = v >> 2, q = v & 3;
        size_t so = ((size_t)kcl * P_DIM + n_base + r) * S_DIM + k0 + q * 8;
        uint32_t d = st + OFF_B + r * ROWB + q * 16;
        if (!tail || q < 2) CP16(d, g_wh + so);
        else                ZERO16(d);
    }
}

__global__ __launch_bounds__(128, 4)
void gemm_kernel(const int* __restrict__ clusters,
                 const float* __restrict__ bias,
                 float* __restrict__ out) {
    extern __shared__ char smem[];
    const uint32_t sbase = smem_u32(smem);
    const int tid  = threadIdx.x;
    const int lane = tid & 31;
    const int wid  = tid >> 5;
    const int warpM = wid & 1;      // 2 M-warps (m32 each)
    const int warpN = wid >> 1;     // 2 N-warps (n56 each)
    const int mrow0 = warpM * 32;
    const int nrow0 = warpN * 56;

    const int ch     = blockIdx.y;           // channel
    const int n_base = blockIdx.x * TILE_N;

    int kcl = clusters[ch];
    kcl = min(max(kcl, 0), NCLUST - 1);

    float acc[2][7][4] = {};

    // ldmatrix base addresses (stage 0; add stage offset per chunk).
    const uint32_t a_addr0 = sbase + OFF_A +
        (uint32_t)(mrow0 + (lane & 15)) * ROWB + ((lane >> 4) << 4);
    const uint32_t b_addr_pair0 = sbase + OFF_B +
        (uint32_t)(nrow0 + ((lane >> 4) << 3) + (lane & 7)) * ROWB +
        (((lane >> 3) & 1) << 4);
    const uint32_t b_addr_last0 = sbase + OFF_B +
        (uint32_t)(nrow0 + 48 + (lane & 7)) * ROWB + (((lane >> 3) & 1) << 4);

    // prologue: stages 0..NSTAGES-2
    #pragma unroll
    for (int s = 0; s < NSTAGES - 1; ++s) {
        load_stage(sbase + s * STAGE_B, s * KC, false, ch, kcl, n_base, tid);
        CP_COMMIT();
    }

    for (int chunk = 0; chunk < NCHUNKS; ++chunk) {
        CP_WAIT(NSTAGES - 2);
        __syncthreads();

        const int nx = chunk + NSTAGES - 1;
        if (nx < NCHUNKS)
            load_stage(sbase + (nx & (NSTAGES - 1)) * STAGE_B, nx * KC,
                       nx == NCHUNKS - 1, ch, kcl, n_base, tid);
        CP_COMMIT();

        const uint32_t so = (uint32_t)(chunk & (NSTAGES - 1)) * STAGE_B;

        // Prefetch ALL fragments for both ks halves, then run all MMAs:
        // the ks=1 LDSM burst overlaps the ks=0 MMA block within this warp.
        uint32_t ah[2][2][4];
        uint32_t bh[2][7][2];
        #pragma unroll
        for (int ks = 0; ks < 2; ++ks) {
            const int kb = ks * 32;
            LDSM4(ah[ks][0], a_addr0 + so + kb);
            LDSM4(ah[ks][1], a_addr0 + so + kb + 16 * ROWB);
            #pragma unroll
            for (int p = 0; p < 3; ++p) {
                uint32_t a = b_addr_pair0 + so + kb + (uint32_t)p * 16 * ROWB;
                uint32_t r4[4];
                LDSM4(r4, a);
                bh[ks][2*p][0] = r4[0]; bh[ks][2*p][1] = r4[1];
                bh[ks][2*p+1][0] = r4[2]; bh[ks][2*p+1][1] = r4[3];
            }
            LDSM2(bh[ks][6], b_addr_last0 + so + kb);
        }

        #pragma unroll
        for (int ks = 0; ks < 2; ++ks)
            #pragma unroll
            for (int mf = 0; mf < 2; ++mf)
                #pragma unroll
                for (int nf = 0; nf < 7; ++nf)
                    MMA(acc[mf][nf], ah[ks][mf], bh[ks][nf]);
    }

    // epilogue: bias + store
    const float* biasrow = bias + (size_t)kcl * P_DIM + n_base + nrow0;
    #pragma unroll
    for (int mf = 0; mf < 2; ++mf) {
        const int b0 = mrow0 + mf * 16 + (lane >> 2);   // batch rows b0, b0+8
        float* o0 = out + ((size_t)b0 * C_DIM + ch) * P_DIM + n_base + nrow0;
        float* o1 = o0 + (size_t)8 * C_DIM * P_DIM;
        #pragma unroll
        for (int nf = 0; nf < 7; ++nf) {
            const int col = nf * 8 + (lane & 3) * 2;
            float2 bb = *(const float2*)(biasrow + col);
            float2 v0, v1;
            v0.x = acc[mf][nf][0] + bb.x;
            v0.y = acc[mf][nf][1] + bb.y;
            v1.x = acc[mf][nf][2] + bb.x;
            v1.y = acc[mf][nf][3] + bb.y;
            *(float2*)(o0 + col) = v0;
            *(float2*)(o1 + col) = v1;
        }
    }
}

extern "C" void kernel_launch(void* const* d_in, const int* in_sizes, int n_in,
                              void* d_out, int out_size) {
    const float* x        = (const float*)d_in[0];
    const int*   clusters = (const int*)d_in[1];
    const float* W        = (const float*)d_in[2];
    const float* bias     = (const float*)d_in[3];
    float*       out      = (float*)d_out;

    cudaFuncSetAttribute(gemm_kernel, cudaFuncAttributeMaxDynamicSharedMemorySize, SMEM_TOTAL);

    convert_x<<<(int)(((size_t)B_DIM*C_DIM*S_DIM/8 + 255)/256), 256>>>(x);
    convert_w<<<(int)(((size_t)NCLUST*P_DIM*S_DIM/4 + 255)/256), 256>>>(W);
    gemm_kernel<<<dim3(3, C_DIM), 128, SMEM_TOTAL>>>(clusters, bias, out);
}

// round 15
// speedup vs baseline: 1.3864x; 1.3705x over previous
#include <cuda_runtime.h>
#include <cuda_fp16.h>
#include <cstdint>

// ClusteredLinear via fp16 mma.sync GEMM, one channel per CTA.
// out[b,c,p] = sum_s x[b,c,s]*W[cl[c],p,s] + bias[cl[c],p]
// R14: exact R10 gemm (128 thr / 4 warps, 2Mx2N m32n56, KC=32, 4 stages,
// 4 CTAs/SM, per-ks fragment loads — R13's both-ks prefetch spilled regs and
// regressed 50%) + the faster uint4 convert_x from R13.
// Single-pass fp16 (x,W rounded, fp32 accum): rel_err ~3.0e-4 measured.

#define B_DIM 64
#define C_DIM 862
#define S_DIM 720
#define P_DIM 336
#define NCLUST 8

#define TILE_N 112
#define KC 32
#define NCHUNKS 23          // 22 full + 16-elem zero-padded tail
#define NSTAGES 4

#define ROWB 80                       // padded smem row stride (bytes)
#define OFF_A 0
#define OFF_B (64*ROWB)               // 5120
#define STAGE_B (OFF_B + TILE_N*ROWB)    // 14080
#define SMEM_TOTAL (NSTAGES*STAGE_B)     // 56320

// ---- scratch ----
__device__ __half g_xh[(size_t)B_DIM*C_DIM*S_DIM];
__device__ __half g_wh[(size_t)NCLUST*P_DIM*S_DIM];

// ---- PTX helpers (family-portable) ----
__device__ __forceinline__ uint32_t smem_u32(const void* p) {
    uint32_t a;
    asm("{ .reg .u64 t; cvta.to.shared.u64 t, %1; cvt.u32.u64 %0, t; }" : "=r"(a) : "l"(p));
    return a;
}
__device__ __forceinline__ uint32_t h2_bits(__half2 h) {
    return *reinterpret_cast<uint32_t*>(&h);
}
#define CP16(dst,src) asm volatile("cp.async.cg.shared.global [%0], [%1], 16;" :: "r"(dst), "l"(src) : "memory")
#define CP_COMMIT()   asm volatile("cp.async.commit_group;" ::: "memory")
#define CP_WAIT(n)    asm volatile("cp.async.wait_group %0;" :: "n"(n) : "memory")
#define ZERO16(a)     asm volatile("st.shared.v4.b32 [%0], {%1,%1,%1,%1};" :: "r"(a), "r"(0) : "memory")

#define LDSM4(r, a) asm volatile("ldmatrix.sync.aligned.m8n8.x4.shared.b16 {%0,%1,%2,%3}, [%4];" \
    : "=r"((r)[0]),"=r"((r)[1]),"=r"((r)[2]),"=r"((r)[3]) : "r"(a))
#define LDSM2(r, a) asm volatile("ldmatrix.sync.aligned.m8n8.x2.shared.b16 {%0,%1}, [%2];" \
    : "=r"((r)[0]),"=r"((r)[1]) : "r"(a))
#define MMA(c, a, b) asm volatile( \
    "mma.sync.aligned.m16n8k16.row.col.f32.f16.f16.f32 " \
    "{%0,%1,%2,%3},{%4,%5,%6,%7},{%8,%9},{%0,%1,%2,%3};" \
    : "+f"((c)[0]),"+f"((c)[1]),"+f"((c)[2]),"+f"((c)[3]) \
    : "r"((a)[0]),"r"((a)[1]),"r"((a)[2]),"r"((a)[3]),"r"((b)[0]),"r"((b)[1]))

// ---- prep kernels ----
__global__ void convert_x(const float* __restrict__ src) {
    size_t i = (size_t)blockIdx.x * blockDim.x + threadIdx.x;
    const size_t n8 = (size_t)B_DIM * C_DIM * S_DIM / 8;
    if (i >= n8) return;
    float4 v0 = ((const float4*)src)[2 * i];
    float4 v1 = ((const float4*)src)[2 * i + 1];
    uint4 o;
    o.x = h2_bits(__floats2half2_rn(v0.x, v0.y));
    o.y = h2_bits(__floats2half2_rn(v0.z, v0.w));
    o.z = h2_bits(__floats2half2_rn(v1.x, v1.y));
    o.w = h2_bits(__floats2half2_rn(v1.z, v1.w));
    ((uint4*)g_xh)[i] = o;
}
__global__ void convert_w(const float* __restrict__ src) {
    size_t i = (size_t)blockIdx.x * blockDim.x + threadIdx.x;
    const size_t n4 = (size_t)NCLUST * P_DIM * S_DIM / 4;
    if (i >= n4) return;
    float4 v = ((const float4*)src)[i];
    uint2 o;
    o.x = h2_bits(__floats2half2_rn(v.x, v.y));
    o.y = h2_bits(__floats2half2_rn(v.z, v.w));
    ((uint2*)g_wh)[i] = o;
}

// ---- GEMM ----
__device__ __forceinline__ void load_stage(uint32_t st, int k0, bool tail,
                                           int ch, int kcl,
                                           int n_base, int tid) {
    // A: 64 rows x 64B of K. 256 slots over 128 threads.
    #pragma unroll
    for (int v = tid; v < 256; v += 128) {
        int r = v >> 2, q = v & 3;
        size_t so = ((size_t)r * C_DIM + ch) * S_DIM + k0 + q * 8;
        uint32_t d = st + OFF_A + r * ROWB + q * 16;
        if (!tail || q < 2) CP16(d, g_xh + so);
        else                ZERO16(d);
    }
    // B: 112 rows x 64B of K. 448 slots over 128 threads.
    #pragma unroll
    for (int v = tid; v < 448; v += 128) {
        int r = v >> 2, q = v & 3;
        size_t so = ((size_t)kcl * P_DIM + n_base + r) * S_DIM + k0 + q * 8;
        uint32_t d = st + OFF_B + r * ROWB + q * 16;
        if (!tail || q < 2) CP16(d, g_wh + so);
        else                ZERO16(d);
    }
}

__global__ __launch_bounds__(128, 4)
void gemm_kernel(const int* __restrict__ clusters,
                 const float* __restrict__ bias,
                 float* __restrict__ out) {
    extern __shared__ char smem[];
    const uint32_t sbase = smem_u32(smem);
    const int tid  = threadIdx.x;
    const int lane = tid & 31;
    const int wid  = tid >> 5;
    const int warpM = wid & 1;      // 2 M-warps (m32 each)
    const int warpN = wid >> 1;     // 2 N-warps (n56 each)
    const int mrow0 = warpM * 32;
    const int nrow0 = warpN * 56;

    const int ch     = blockIdx.y;           // channel
    const int n_base = blockIdx.x * TILE_N;

    int kcl = clusters[ch];
    kcl = min(max(kcl, 0), NCLUST - 1);

    float acc[2][7][4] = {};

    // ldmatrix base addresses (stage 0; add stage offset per chunk).
    const uint32_t a_addr0 = sbase + OFF_A +
        (uint32_t)(mrow0 + (lane & 15)) * ROWB + ((lane >> 4) << 4);
    const uint32_t b_addr_pair0 = sbase + OFF_B +
        (uint32_t)(nrow0 + ((lane >> 4) << 3) + (lane & 7)) * ROWB +
        (((lane >> 3) & 1) << 4);
    const uint32_t b_addr_last0 = sbase + OFF_B +
        (uint32_t)(nrow0 + 48 + (lane & 7)) * ROWB + (((lane >> 3) & 1) << 4);

    // prologue: stages 0..NSTAGES-2
    #pragma unroll
    for (int s = 0; s < NSTAGES - 1; ++s) {
        load_stage(sbase + s * STAGE_B, s * KC, false, ch, kcl, n_base, tid);
        CP_COMMIT();
    }

    for (int chunk = 0; chunk < NCHUNKS; ++chunk) {
        CP_WAIT(NSTAGES - 2);
        __syncthreads();

        const int nx = chunk + NSTAGES - 1;
        if (nx < NCHUNKS)
            load_stage(sbase + (nx & (NSTAGES - 1)) * STAGE_B, nx * KC,
                       nx == NCHUNKS - 1, ch, kcl, n_base, tid);
        CP_COMMIT();

        const uint32_t so = (uint32_t)(chunk & (NSTAGES - 1)) * STAGE_B;
        #pragma unroll
        for (int ks = 0; ks < 2; ++ks) {
            const int kb = ks * 32;
            uint32_t ah[2][4];
            LDSM4(ah[0], a_addr0 + so + kb);
            LDSM4(ah[1], a_addr0 + so + kb + 16 * ROWB);

            uint32_t bh[7][2];
            #pragma unroll
            for (int p = 0; p < 3; ++p) {
                uint32_t a = b_addr_pair0 + so + kb + (uint32_t)p * 16 * ROWB;
                uint32_t r4[4];
                LDSM4(r4, a);
                bh[2*p][0] = r4[0]; bh[2*p][1] = r4[1];
                bh[2*p+1][0] = r4[2]; bh[2*p+1][1] = r4[3];
            }
            LDSM2(bh[6], b_addr_last0 + so + kb);

            #pragma unroll
            for (int mf = 0; mf < 2; ++mf)
                #pragma unroll
                for (int nf = 0; nf < 7; ++nf)
                    MMA(acc[mf][nf], ah[mf], bh[nf]);
        }
    }

    // epilogue: bias + store
    const float* biasrow = bias + (size_t)kcl * P_DIM + n_base + nrow0;
    #pragma unroll
    for (int mf = 0; mf < 2; ++mf) {
        const int b0 = mrow0 + mf * 16 + (lane >> 2);   // batch rows b0, b0+8
        float* o0 = out + ((size_t)b0 * C_DIM + ch) * P_DIM + n_base + nrow0;
        float* o1 = o0 + (size_t)8 * C_DIM * P_DIM;
        #pragma unroll
        for (int nf = 0; nf < 7; ++nf) {
            const int col = nf * 8 + (lane & 3) * 2;
            float2 bb = *(const float2*)(biasrow + col);
            float2 v0, v1;
            v0.x = acc[mf][nf][0] + bb.x;
            v0.y = acc[mf][nf][1] + bb.y;
            v1.x = acc[mf][nf][2] + bb.x;
            v1.y = acc[mf][nf][3] + bb.y;
            *(float2*)(o0 + col) = v0;
            *(float2*)(o1 + col) = v1;
        }
    }
}

extern "C" void kernel_launch(void* const* d_in, const int* in_sizes, int n_in,
                              void* d_out, int out_size) {
    const float* x        = (const float*)d_in[0];
    const int*   clusters = (const int*)d_in[1];
    const float* W        = (const float*)d_in[2];
    const float* bias     = (const float*)d_in[3];
    float*       out      = (float*)d_out;

    cudaFuncSetAttribute(gemm_kernel, cudaFuncAttributeMaxDynamicSharedMemorySize, SMEM_TOTAL);

    convert_x<<<(int)(((size_t)B_DIM*C_DIM*S_DIM/8 + 255)/256), 256>>>(x);
    convert_w<<<(int)(((size_t)NCLUST*P_DIM*S_DIM/4 + 255)/256), 256>>>(W);
    gemm_kernel<<<dim3(3, C_DIM), 128, SMEM_TOTAL>>>(clusters, bias, out);
}

// round 17
// speedup vs baseline: 1.4959x; 1.0790x over previous
#include <cuda_runtime.h>
#include <cuda_fp16.h>
#include <cstdint>

// ClusteredLinear via fp16 mma.sync GEMM, one channel per CTA.
// out[b,c,p] = sum_s x[b,c,s]*W[cl[c],p,s] + bias[cl[c],p]
// R15: R14 gemm config (128 thr / 4 warps, 2Mx2N m32n56, KC=32, 4 stages,
// 4 CTAs/SM) with convert_x FUSED into the gemm: x is read fp32 via LDG one
// chunk ahead into registers, converted to fp16 in-register, and STS'd into
// the A stage slot at the same point the old cp.async wrote it. Eliminates
// the 31us convert_x kernel and its 238MB DRAM round trip.
// Single-pass fp16 (x,W rounded, fp32 accum): rel_err ~3.0e-4 measured.

#define B_DIM 64
#define C_DIM 862
#define S_DIM 720
#define P_DIM 336
#define NCLUST 8

#define TILE_N 112
#define KC 32
#define NCHUNKS 23          // 22 full + 16-elem zero-padded tail
#define NSTAGES 4

#define ROWB 80                       // padded smem row stride (bytes)
#define OFF_A 0
#define OFF_B (64*ROWB)               // 5120
#define STAGE_B (OFF_B + TILE_N*ROWB)    // 14080
#define SMEM_TOTAL (NSTAGES*STAGE_B)     // 56320

// ---- scratch ----
__device__ __half g_wh[(size_t)NCLUST*P_DIM*S_DIM];

// ---- PTX helpers (family-portable) ----
__device__ __forceinline__ uint32_t smem_u32(const void* p) {
    uint32_t a;
    asm("{ .reg .u64 t; cvta.to.shared.u64 t, %1; cvt.u32.u64 %0, t; }" : "=r"(a) : "l"(p));
    return a;
}
__device__ __forceinline__ uint32_t h2_bits(__half2 h) {
    return *reinterpret_cast<uint32_t*>(&h);
}
#define CP16(dst,src) asm volatile("cp.async.cg.shared.global [%0], [%1], 16;" :: "r"(dst), "l"(src) : "memory")
#define CP_COMMIT()   asm volatile("cp.async.commit_group;" ::: "memory")
#define CP_WAIT(n)    asm volatile("cp.async.wait_group %0;" :: "n"(n) : "memory")
#define ZERO16(a)     asm volatile("st.shared.v4.b32 [%0], {%1,%1,%1,%1};" :: "r"(a), "r"(0) : "memory")
#define STS64(a,v0,v1) asm volatile("st.shared.v2.b32 [%0], {%1,%2};" :: "r"(a), "r"(v0), "r"(v1) : "memory")

#define LDSM4(r, a) asm volatile("ldmatrix.sync.aligned.m8n8.x4.shared.b16 {%0,%1,%2,%3}, [%4];" \
    : "=r"((r)[0]),"=r"((r)[1]),"=r"((r)[2]),"=r"((r)[3]) : "r"(a))
#define LDSM2(r, a) asm volatile("ldmatrix.sync.aligned.m8n8.x2.shared.b16 {%0,%1}, [%2];" \
    : "=r"((r)[0]),"=r"((r)[1]) : "r"(a))
#define MMA(c, a, b) asm volatile( \
    "mma.sync.aligned.m16n8k16.row.col.f32.f16.f16.f32 " \
    "{%0,%1,%2,%3},{%4,%5,%6,%7},{%8,%9},{%0,%1,%2,%3};" \
    : "+f"((c)[0]),"+f"((c)[1]),"+f"((c)[2]),"+f"((c)[3]) \
    : "r"((a)[0]),"r"((a)[1]),"r"((a)[2]),"r"((a)[3]),"r"((b)[0]),"r"((b)[1]))

// ---- prep kernel (W only; x conversion fused into gemm) ----
__global__ void convert_w(const float* __restrict__ src) {
    size_t i = (size_t)blockIdx.x * blockDim.x + threadIdx.x;
    const size_t n4 = (size_t)NCLUST * P_DIM * S_DIM / 4;
    if (i >= n4) return;
    float4 v = ((const float4*)src)[i];
    uint2 o;
    o.x = h2_bits(__floats2half2_rn(v.x, v.y));
    o.y = h2_bits(__floats2half2_rn(v.z, v.w));
    ((uint2*)g_wh)[i] = o;
}

// ---- GEMM ----
// A chunk held in regs: thread owns q = tid&7 (16B fp32 column) of rows
// r0 + {0,16,32,48}. Tail chunk (16 valid k): q<4 valid, uniform per thread.
__device__ __forceinline__ void ldg_A(float4* aq, const float* __restrict__ x,
                                      int ch, int k0, int tid, bool tail) {
    const int q = tid & 7, r0 = tid >> 3;
    if (!tail || q < 4) {
        #pragma unroll
        for (int j = 0; j < 4; ++j) {
            int r = r0 + 16 * j;
            aq[j] = *(const float4*)(x + ((size_t)r * C_DIM + ch) * S_DIM + k0 + q * 4);
        }
    }
}
__device__ __forceinline__ void sts_A(const float4* aq, uint32_t st, int tid, bool tail) {
    const int q = tid & 7, r0 = tid >> 3;
    #pragma unroll
    for (int j = 0; j < 4; ++j) {
        uint32_t d = st + OFF_A + (uint32_t)(r0 + 16 * j) * ROWB + q * 8;
        if (!tail || q < 4) {
            uint32_t lo = h2_bits(__floats2half2_rn(aq[j].x, aq[j].y));
            uint32_t hi = h2_bits(__floats2half2_rn(aq[j].z, aq[j].w));
            STS64(d, lo, hi);
        } else {
            STS64(d, 0u, 0u);
        }
    }
}
__device__ __forceinline__ void load_B(uint32_t st, int k0, bool tail,
                                       int kcl, int n_base, int tid) {
    // B: 112 rows x 64B of K (fp16). 448 slots over 128 threads.
    #pragma unroll
    for (int v = tid; v < 448; v += 128) {
        int r = v >> 2, q = v & 3;
        size_t so = ((size_t)kcl * P_DIM + n_base + r) * S_DIM + k0 + q * 8;
        uint32_t d = st + OFF_B + r * ROWB + q * 16;
        if (!tail || q < 2) CP16(d, g_wh + so);
        else                ZERO16(d);
    }
}

__global__ __launch_bounds__(128, 4)
void gemm_kernel(const float* __restrict__ x,
                 const int* __restrict__ clusters,
                 const float* __restrict__ bias,
                 float* __restrict__ out) {
    extern __shared__ char smem[];
    const uint32_t sbase = smem_u32(smem);
    const int tid  = threadIdx.x;
    const int lane = tid & 31;
    const int wid  = tid >> 5;
    const int warpM = wid & 1;      // 2 M-warps (m32 each)
    const int warpN = wid >> 1;     // 2 N-warps (n56 each)
    const int mrow0 = warpM * 32;
    const int nrow0 = warpN * 56;

    const int ch     = blockIdx.y;           // channel
    const int n_base = blockIdx.x * TILE_N;

    int kcl = clusters[ch];
    kcl = min(max(kcl, 0), NCLUST - 1);

    float acc[2][7][4] = {};

    // ldmatrix base addresses (stage 0; add stage offset per chunk).
    const uint32_t a_addr0 = sbase + OFF_A +
        (uint32_t)(mrow0 + (lane & 15)) * ROWB + ((lane >> 4) << 4);
    const uint32_t b_addr_pair0 = sbase + OFF_B +
        (uint32_t)(nrow0 + ((lane >> 4) << 3) + (lane & 7)) * ROWB +
        (((lane >> 3) & 1) << 4);
    const uint32_t b_addr_last0 = sbase + OFF_B +
        (uint32_t)(nrow0 + 48 + (lane & 7)) * ROWB + (((lane >> 3) & 1) << 4);

    // prologue: stages 0..2 (A synchronous LDG->cvt->STS; B cp.async)
    #pragma unroll
    for (int s = 0; s < NSTAGES - 1; ++s) {
        float4 atmp[4];
        ldg_A(atmp, x, ch, s * KC, tid, false);
        sts_A(atmp, sbase + s * STAGE_B, tid, false);
        load_B(sbase + s * STAGE_B, s * KC, false, kcl, n_base, tid);
        CP_COMMIT();
    }
    // A regs for chunk 3
    float4 aq[4];
    ldg_A(aq, x, ch, 3 * KC, tid, false);

    for (int chunk = 0; chunk < NCHUNKS; ++chunk) {
        CP_WAIT(NSTAGES - 2);
        __syncthreads();

        const int nx = chunk + NSTAGES - 1;
        if (nx < NCHUNKS) {
            const uint32_t st = sbase + (nx & (NSTAGES - 1)) * STAGE_B;
            const bool tail = (nx == NCHUNKS - 1);
            sts_A(aq, st, tid, tail);
            load_B(st, nx * KC, tail, kcl, n_base, tid);
        }
        CP_COMMIT();
        if (chunk + NSTAGES < NCHUNKS)
            ldg_A(aq, x, ch, (chunk + NSTAGES) * KC, tid,
                  chunk + NSTAGES == NCHUNKS - 1);

        const uint32_t so = (uint32_t)(chunk & (NSTAGES - 1)) * STAGE_B;
        #pragma unroll
        for (int ks = 0; ks < 2; ++ks) {
            const int kb = ks * 32;
            uint32_t ah[2][4];
            LDSM4(ah[0], a_addr0 + so + kb);
            LDSM4(ah[1], a_addr0 + so + kb + 16 * ROWB);

            uint32_t bh[7][2];
            #pragma unroll
            for (int p = 0; p < 3; ++p) {
                uint32_t a = b_addr_pair0 + so + kb + (uint32_t)p * 16 * ROWB;
                uint32_t r4[4];
                LDSM4(r4, a);
                bh[2*p][0] = r4[0]; bh[2*p][1] = r4[1];
                bh[2*p+1][0] = r4[2]; bh[2*p+1][1] = r4[3];
            }
            LDSM2(bh[6], b_addr_last0 + so + kb);

            #pragma unroll
            for (int mf = 0; mf < 2; ++mf)
                #pragma unroll
                for (int nf = 0; nf < 7; ++nf)
                    MMA(acc[mf][nf], ah[mf], bh[nf]);
        }
    }

    // epilogue: bias + store
    const float* biasrow = bias + (size_t)kcl * P_DIM + n_base + nrow0;
    #pragma unroll
    for (int mf = 0; mf < 2; ++mf) {
        const int b0 = mrow0 + mf * 16 + (lane >> 2);   // batch rows b0, b0+8
        float* o0 = out + ((size_t)b0 * C_DIM + ch) * P_DIM + n_base + nrow0;
        float* o1 = o0 + (size_t)8 * C_DIM * P_DIM;
        #pragma unroll
        for (int nf = 0; nf < 7; ++nf) {
            const int col = nf * 8 + (lane & 3) * 2;
            float2 bb = *(const float2*)(biasrow + col);
            float2 v0, v1;
            v0.x = acc[mf][nf][0] + bb.x;
            v0.y = acc[mf][nf][1] + bb.y;
            v1.x = acc[mf][nf][2] + bb.x;
            v1.y = acc[mf][nf][3] + bb.y;
            *(float2*)(o0 + col) = v0;
            *(float2*)(o1 + col) = v1;
        }
    }
}

extern "C" void kernel_launch(void* const* d_in, const int* in_sizes, int n_in,
                              void* d_out, int out_size) {
    const float* x        = (const float*)d_in[0];
    const int*   clusters = (const int*)d_in[1];
    const float* W        = (const float*)d_in[2];
    const float* bias     = (const float*)d_in[3];
    float*       out      = (float*)d_out;

    cudaFuncSetAttribute(gemm_kernel, cudaFuncAttributeMaxDynamicSharedMemorySize, SMEM_TOTAL);

    convert_w<<<(int)(((size_t)NCLUST*P_DIM*S_DIM/4 + 255)/256), 256>>>(W);
    gemm_kernel<<<dim3(3, C_DIM), 128, SMEM_TOTAL>>>(x, clusters, bias, out);
}